// round 14
// baseline (speedup 1.0000x reference)
#include <cuda_runtime.h>
#include <cuda_bf16.h>
#include <cstdint>

// Problem constants
#define BATCH 2
#define SEQ   2048
#define DIM   1024
#define HEADS 16
#define HD    64
#define MROWS (BATCH*SEQ)      // 4096
#define NQKV  (3*DIM)          // 3072

// Scratch (device globals: allocation-free)
__device__ float g_q[BATCH*HEADS*SEQ*HD];     // [b,h,s,d]
__device__ float g_k[BATCH*HEADS*SEQ*HD];
__device__ float g_v[BATCH*HEADS*SEQ*HD];
__device__ float g_attn[BATCH*SEQ*DIM];       // [b,s,h*64+d] (tf32-rounded)
__device__ float g_xr[MROWS*DIM];             // x rounded to tf32
__device__ float g_wqkvr[NQKV*DIM];           // w_qkv rounded to tf32
__device__ float g_wprojr[DIM*DIM];           // w_proj rounded to tf32

// ---------------------------------------------------------------------------
// helpers
// ---------------------------------------------------------------------------
__device__ __forceinline__ uint32_t f2tf32(float f) {
    uint32_t u;
    asm("cvt.rna.tf32.f32 %0, %1;" : "=r"(u) : "f"(f));
    return u;
}
__device__ __forceinline__ float ftf32(float f) { return __uint_as_float(f2tf32(f)); }

__device__ __forceinline__ float ex2(float x) {
    float r;
    asm("ex2.approx.f32 %0, %1;" : "=f"(r) : "f"(x));
    return r;
}

__device__ __forceinline__ void mma_tf32(float c[4], const uint32_t a[4], const uint32_t b[2]) {
    asm volatile(
        "mma.sync.aligned.m16n8k8.row.col.f32.tf32.tf32.f32 "
        "{%0,%1,%2,%3},{%4,%5,%6,%7},{%8,%9},{%0,%1,%2,%3};\n"
        : "+f"(c[0]), "+f"(c[1]), "+f"(c[2]), "+f"(c[3])
        : "r"(a[0]), "r"(a[1]), "r"(a[2]), "r"(a[3]), "r"(b[0]), "r"(b[1]));
}

// ---------------------------------------------------------------------------
// Fused tf32 rounding pre-pass (RNA) for x, w_qkv, w_proj in ONE launch.
// ---------------------------------------------------------------------------
#define N4X (MROWS*DIM/4)     // 1048576
#define N4Q (NQKV*DIM/4)      // 786432
#define N4P (DIM*DIM/4)       // 262144
#define N4TOT (N4X + N4Q + N4P)

__global__ __launch_bounds__(256)
void round3_kernel(const float* __restrict__ x,  float* __restrict__ xo,
                   const float* __restrict__ wq, float* __restrict__ wqo,
                   const float* __restrict__ wp, float* __restrict__ wpo)
{
    int i = blockIdx.x * 256 + threadIdx.x;
    const float4* in; float4* out; int j;
    if (i < N4X)            { in = (const float4*)x;  out = (float4*)xo;  j = i; }
    else if (i < N4X + N4Q) { in = (const float4*)wq; out = (float4*)wqo; j = i - N4X; }
    else if (i < N4TOT)     { in = (const float4*)wp; out = (float4*)wpo; j = i - N4X - N4Q; }
    else return;
    float4 v = in[j];
    out[j] = make_float4(ftf32(v.x), ftf32(v.y), ftf32(v.z), ftf32(v.w));
}

// ---------------------------------------------------------------------------
// TF32 GEMM v2 (occupancy-optimized): C[m,n] = sum_k A[m,k]*W[n,k] + bias[n]
// BM=128, BN=64, BK=32, 256 threads, cp.async 2-stage, warp tile 32x32,
// 3 CTAs/SM target (24 warps). A, W pre-rounded to tf32.
// ---------------------------------------------------------------------------
#define PK 36
#define GEMM_SMEM (2*(128+64)*PK*4)   // 55296 bytes

template<int SCATTER>
__global__ __launch_bounds__(256, 3)
void gemm_tf32(const float* __restrict__ A,
               const float* __restrict__ W,
               const float* __restrict__ bias,
               float* __restrict__ out)
{
    extern __shared__ float sm[];
    float* As = sm;               // [2][128][PK]
    float* Bs = sm + 2*128*PK;    // [2][64][PK]

    const int tid  = threadIdx.x;
    const int wid  = tid >> 5;
    const int lane = tid & 31;
    const int m0 = blockIdx.y * 128;
    const int n0 = blockIdx.x * 64;
    const int wm = (wid & 3) * 32;
    const int wn = (wid >> 2) * 32;
    const int tg = lane >> 2;     // 0..7
    const int tk = lane & 3;      // 0..3

    float acc[2][4][4];
#pragma unroll
    for (int mt = 0; mt < 2; ++mt)
#pragma unroll
        for (int nt = 0; nt < 4; ++nt)
#pragma unroll
            for (int c = 0; c < 4; ++c) acc[mt][nt][c] = 0.f;

    const int K = 1024;
    const int NS = K / 32;

    auto stage = [&](int s, int buf) {
        const int k0 = s * 32;
#pragma unroll
        for (int i = 0; i < 4; ++i) {        // A: 128 rows x 32 -> 1024 f4
            const int t   = tid + i * 256;
            const int row = t >> 3;
            const int kc  = (t & 7) << 2;
            uint32_t sa = (uint32_t)__cvta_generic_to_shared(
                &As[buf*128*PK + row*PK + kc]);
            asm volatile("cp.async.cg.shared.global [%0], [%1], 16;\n"
                         :: "r"(sa), "l"(&A[(long)(m0 + row) * K + k0 + kc]));
        }
#pragma unroll
        for (int i = 0; i < 2; ++i) {        // B: 64 rows x 32 -> 512 f4
            const int t   = tid + i * 256;
            const int row = t >> 3;
            const int kc  = (t & 7) << 2;
            uint32_t sb = (uint32_t)__cvta_generic_to_shared(
                &Bs[buf*64*PK + row*PK + kc]);
            asm volatile("cp.async.cg.shared.global [%0], [%1], 16;\n"
                         :: "r"(sb), "l"(&W[(long)(n0 + row) * K + k0 + kc]));
        }
        asm volatile("cp.async.commit_group;\n");
    };

    stage(0, 0);

    for (int s = 0; s < NS; ++s) {
        const int buf = s & 1;
        if (s + 1 < NS) {
            stage(s + 1, buf ^ 1);
            asm volatile("cp.async.wait_group 1;\n");
        } else {
            asm volatile("cp.async.wait_group 0;\n");
        }
        __syncthreads();

        const float* as = &As[buf*128*PK];
        const float* bs = &Bs[buf*64*PK];
#pragma unroll
        for (int k8 = 0; k8 < 32; k8 += 8) {
            uint32_t af[2][4], bf[4][2];
#pragma unroll
            for (int mt = 0; mt < 2; ++mt) {
                const float* p = &as[(wm + mt*16 + tg)*PK + k8 + tk];
                af[mt][0] = __float_as_uint(p[0]);
                af[mt][1] = __float_as_uint(p[8*PK]);
                af[mt][2] = __float_as_uint(p[4]);
                af[mt][3] = __float_as_uint(p[8*PK + 4]);
            }
#pragma unroll
            for (int nt = 0; nt < 4; ++nt) {
                const float* p = &bs[(wn + nt*8 + tg)*PK + k8 + tk];
                bf[nt][0] = __float_as_uint(p[0]);
                bf[nt][1] = __float_as_uint(p[4]);
            }
#pragma unroll
            for (int mt = 0; mt < 2; ++mt)
#pragma unroll
                for (int nt = 0; nt < 4; ++nt)
                    mma_tf32(acc[mt][nt], af[mt], bf[nt]);
        }
        __syncthreads();
    }

    // epilogue (float2 stores)
#pragma unroll
    for (int mt = 0; mt < 2; ++mt) {
#pragma unroll
        for (int nt = 0; nt < 4; ++nt) {
            const int n = n0 + wn + nt*8 + 2*tk;
#pragma unroll
            for (int half = 0; half < 2; ++half) {
                const int m = m0 + wm + mt*16 + tg + half*8;
                const float v0 = acc[mt][nt][half*2]     + bias[n];
                const float v1 = acc[mt][nt][half*2 + 1] + bias[n + 1];
                if (SCATTER) {
                    const int b = m >> 11, sq = m & 2047;
                    const int part = n >> 10, h = (n >> 6) & 15, d = n & 63;
                    float* dst = (part == 0) ? g_q : (part == 1) ? g_k : g_v;
                    *(float2*)&dst[((((long)b*HEADS + h)*SEQ) + sq)*HD + d] =
                        make_float2(ftf32(v0), ftf32(v1));
                } else {
                    *(float2*)&out[(long)m * 1024 + n] = make_float2(v0, v1);
                }
            }
        }
    }
}

// ---------------------------------------------------------------------------
// Flash attention v4: register-resident, base-2 softmax, 1 barrier/iter.
// BQ=128, BKV=64, 256 threads = 8 warps; each warp owns 16 rows.
// ---------------------------------------------------------------------------
#define KP3 68
#define VP3 72
#define PP3 68
#define F3_KOFF 0
#define F3_VOFF (2*64*KP3)
#define F3_POFF (F3_VOFF + 2*64*VP3)
#define F3_SMEM ((F3_POFF + 8*16*PP3)*4)   // 106496 bytes

__global__ __launch_bounds__(256, 2)
void flash4(float* __restrict__ Ob)
{
    extern __shared__ float sm[];
    float* Ksm = sm + F3_KOFF;
    float* Vsm = sm + F3_VOFF;
    float* Psm = sm + F3_POFF;

    const int tid  = threadIdx.x;
    const int wid  = tid >> 5;
    const int lane = tid & 31;
    const int tg = lane >> 2;
    const int tk = lane & 3;
    const int bh = blockIdx.y;
    const int q0 = blockIdx.x * 128;
    const int wm = wid * 16;

    const float* Qg = g_q + ((long)bh*SEQ + q0) * HD;
    const float* Kg = g_k + (long)bh*SEQ*HD;
    const float* Vg = g_v + (long)bh*SEQ*HD;
    float* Pw = Psm + wid*16*PP3;

    const float qs = 0.125f * 1.4426950408889634f;
    uint32_t qf[8][4];
#pragma unroll
    for (int i = 0; i < 8; ++i) {
        const int k = i * 8;
        qf[i][0] = f2tf32(Qg[(wm+tg)*HD   + k+tk]   * qs);
        qf[i][1] = f2tf32(Qg[(wm+tg+8)*HD + k+tk]   * qs);
        qf[i][2] = f2tf32(Qg[(wm+tg)*HD   + k+tk+4] * qs);
        qf[i][3] = f2tf32(Qg[(wm+tg+8)*HD + k+tk+4] * qs);
    }

    float oacc[8][4];
#pragma unroll
    for (int nt = 0; nt < 8; ++nt)
#pragma unroll
        for (int c = 0; c < 4; ++c) oacc[nt][c] = 0.f;
    float m0 = -1e30f, m1 = -1e30f, l0 = 0.f, l1 = 0.f;

    auto stage = [&](int s, int b2) {
        const float* Kt = Kg + (long)s*64*HD;
        const float* Vt = Vg + (long)s*64*HD;
#pragma unroll
        for (int i = 0; i < 4; ++i) {
            const int t = tid + i*256;
            const int r = t >> 4;
            const int c = (t & 15) << 2;
            uint32_t dk = (uint32_t)__cvta_generic_to_shared(
                &Ksm[b2*64*KP3 + r*KP3 + c]);
            asm volatile("cp.async.cg.shared.global [%0], [%1], 16;\n"
                         :: "r"(dk), "l"(&Kt[r*HD + c]));
            uint32_t dv = (uint32_t)__cvta_generic_to_shared(
                &Vsm[b2*64*VP3 + r*VP3 + c]);
            asm volatile("cp.async.cg.shared.global [%0], [%1], 16;\n"
                         :: "r"(dv), "l"(&Vt[r*HD + c]));
        }
        asm volatile("cp.async.commit_group;\n");
    };

    stage(0, 0);

    const int NT = SEQ / 64;
    for (int kt = 0; kt < NT; ++kt) {
        const int buf = kt & 1;
        asm volatile("cp.async.wait_group 0;\n");
        __syncthreads();
        if (kt + 1 < NT) stage(kt + 1, buf ^ 1);

        const float* Kb = &Ksm[buf*64*KP3];
        const float* Vb = &Vsm[buf*64*VP3];

        float sacc[8][4];
#pragma unroll
        for (int nt = 0; nt < 8; ++nt)
#pragma unroll
            for (int c = 0; c < 4; ++c) sacc[nt][c] = 0.f;
#pragma unroll
        for (int i = 0; i < 8; ++i) {
            const int k8 = i * 8;
            uint32_t bf[8][2];
#pragma unroll
            for (int nt = 0; nt < 8; ++nt) {
                const float* p = &Kb[(nt*8 + tg)*KP3 + k8 + tk];
                bf[nt][0] = __float_as_uint(p[0]);
                bf[nt][1] = __float_as_uint(p[4]);
            }
#pragma unroll
            for (int nt = 0; nt < 8; ++nt)
                mma_tf32(sacc[nt], qf[i], bf[nt]);
        }

        float r0 = -1e30f, r1 = -1e30f;
#pragma unroll
        for (int nt = 0; nt < 8; ++nt) {
            r0 = fmaxf(r0, fmaxf(sacc[nt][0], sacc[nt][1]));
            r1 = fmaxf(r1, fmaxf(sacc[nt][2], sacc[nt][3]));
        }
        r0 = fmaxf(r0, __shfl_xor_sync(0xffffffffu, r0, 1));
        r0 = fmaxf(r0, __shfl_xor_sync(0xffffffffu, r0, 2));
        r1 = fmaxf(r1, __shfl_xor_sync(0xffffffffu, r1, 1));
        r1 = fmaxf(r1, __shfl_xor_sync(0xffffffffu, r1, 2));
        const float mn0 = fmaxf(m0, r0);
        const float mn1 = fmaxf(m1, r1);
        const float a0 = ex2(m0 - mn0);
        const float a1 = ex2(m1 - mn1);
        float s0 = 0.f, s1 = 0.f;
#pragma unroll
        for (int nt = 0; nt < 8; ++nt) {
            float p0 = ftf32(ex2(sacc[nt][0] - mn0));
            float p1 = ftf32(ex2(sacc[nt][1] - mn0));
            float p2 = ftf32(ex2(sacc[nt][2] - mn1));
            float p3 = ftf32(ex2(sacc[nt][3] - mn1));
            sacc[nt][0] = p0; sacc[nt][1] = p1;
            sacc[nt][2] = p2; sacc[nt][3] = p3;
            s0 += p0 + p1;
            s1 += p2 + p3;
        }
        s0 += __shfl_xor_sync(0xffffffffu, s0, 1);
        s0 += __shfl_xor_sync(0xffffffffu, s0, 2);
        s1 += __shfl_xor_sync(0xffffffffu, s1, 1);
        s1 += __shfl_xor_sync(0xffffffffu, s1, 2);
        l0 = l0 * a0 + s0;
        l1 = l1 * a1 + s1;
        m0 = mn0; m1 = mn1;
#pragma unroll
        for (int nt = 0; nt < 8; ++nt) {
            oacc[nt][0] *= a0; oacc[nt][1] *= a0;
            oacc[nt][2] *= a1; oacc[nt][3] *= a1;
        }

#pragma unroll
        for (int nt = 0; nt < 8; ++nt) {
            *(float2*)&Pw[tg*PP3     + nt*8 + 2*tk] = make_float2(sacc[nt][0], sacc[nt][1]);
            *(float2*)&Pw[(tg+8)*PP3 + nt*8 + 2*tk] = make_float2(sacc[nt][2], sacc[nt][3]);
        }
        __syncwarp();

#pragma unroll
        for (int i = 0; i < 8; ++i) {
            const int k8 = i * 8;
            uint32_t af[4];
            af[0] = __float_as_uint(Pw[tg*PP3     + k8 + tk]);
            af[1] = __float_as_uint(Pw[(tg+8)*PP3 + k8 + tk]);
            af[2] = __float_as_uint(Pw[tg*PP3     + k8 + tk + 4]);
            af[3] = __float_as_uint(Pw[(tg+8)*PP3 + k8 + tk + 4]);
            uint32_t bf[8][2];
#pragma unroll
            for (int nt = 0; nt < 8; ++nt) {
                bf[nt][0] = __float_as_uint(Vb[(k8+tk)*VP3   + nt*8 + tg]);
                bf[nt][1] = __float_as_uint(Vb[(k8+tk+4)*VP3 + nt*8 + tg]);
            }
#pragma unroll
            for (int nt = 0; nt < 8; ++nt)
                mma_tf32(oacc[nt], af, bf[nt]);
        }
    }

    const int b = bh >> 4, h = bh & 15;
    const float i0 = 1.f / l0;
    const float i1 = 1.f / l1;
    const long row0 = (long)b*SEQ + q0 + wm + tg;
    const long row1 = row0 + 8;
#pragma unroll
    for (int nt = 0; nt < 8; ++nt) {
        const int col = h*HD + nt*8 + 2*tk;
        *(float2*)&Ob[row0*DIM + col] =
            make_float2(ftf32(oacc[nt][0]*i0), ftf32(oacc[nt][1]*i0));
        *(float2*)&Ob[row1*DIM + col] =
            make_float2(ftf32(oacc[nt][2]*i1), ftf32(oacc[nt][3]*i1));
    }
}

// ---------------------------------------------------------------------------
extern "C" void kernel_launch(void* const* d_in, const int* in_sizes, int n_in,
                              void* d_out, int out_size)
{
    const float* x      = (const float*)d_in[0];
    const float* w_qkv  = (const float*)d_in[1];
    const float* b_qkv  = (const float*)d_in[2];
    const float* w_proj = (const float*)d_in[3];
    const float* b_proj = (const float*)d_in[4];
    float* out = (float*)d_out;

    float *attn_ptr = nullptr, *xr = nullptr, *wqkvr = nullptr, *wprojr = nullptr;
    cudaGetSymbolAddress((void**)&attn_ptr, g_attn);
    cudaGetSymbolAddress((void**)&xr, g_xr);
    cudaGetSymbolAddress((void**)&wqkvr, g_wqkvr);
    cudaGetSymbolAddress((void**)&wprojr, g_wprojr);

    cudaFuncSetAttribute(gemm_tf32<1>,
        cudaFuncAttributeMaxDynamicSharedMemorySize, GEMM_SMEM);
    cudaFuncSetAttribute(gemm_tf32<0>,
        cudaFuncAttributeMaxDynamicSharedMemorySize, GEMM_SMEM);
    cudaFuncSetAttribute(flash4,
        cudaFuncAttributeMaxDynamicSharedMemorySize, F3_SMEM);

    // 0) fused tf32 rounding pre-pass (RNA) for all GEMM operands
    round3_kernel<<<(N4TOT + 255)/256, 256>>>(x, xr, w_qkv, wqkvr, w_proj, wprojr);

    // 1) QKV GEMM + bias -> scatter into Q/K/V [b,h,s,d] (tf32-rounded)
    {
        dim3 grid(NQKV/64, MROWS/128);    // (48, 32)
        gemm_tf32<1><<<grid, 256, GEMM_SMEM>>>(xr, wqkvr, b_qkv, nullptr);
    }
    // 2) flash attention v4 -> g_attn [b,s,D] (tf32-rounded)
    {
        dim3 grid(SEQ/128, BATCH*HEADS);  // (16, 32)
        flash4<<<grid, 256, F3_SMEM>>>(attn_ptr);
    }
    // 3) output projection + bias -> d_out
    {
        dim3 grid(DIM/64, MROWS/128);     // (16, 32)
        gemm_tf32<0><<<grid, 256, GEMM_SMEM>>>(attn_ptr, wprojr, b_proj, out);
    }
}

// round 16
// speedup vs baseline: 1.1589x; 1.1589x over previous
#include <cuda_runtime.h>
#include <cuda_bf16.h>
#include <cuda_fp16.h>
#include <cstdint>

// Problem constants
#define BATCH 2
#define SEQ   2048
#define DIM   1024
#define HEADS 16
#define HD    64
#define MROWS (BATCH*SEQ)      // 4096
#define NQKV  (3*DIM)          // 3072

// Scratch (device globals: allocation-free)
__device__ float  g_q[BATCH*HEADS*SEQ*HD];    // [b,h,s,d] fp32 (tf32-rounded)
__device__ float  g_k[BATCH*HEADS*SEQ*HD];    // [b,h,s,d] fp32 (tf32-rounded)
__device__ __half g_vh[BATCH*HEADS*SEQ*HD];   // [b,h,s,d] fp16
__device__ __half g_vt[BATCH*HEADS*HD*SEQ];   // [b,h,d,s] fp16 (transposed)
__device__ float  g_attn[BATCH*SEQ*DIM];      // [b,s,h*64+d] (tf32-rounded)
__device__ float  g_xr[MROWS*DIM];            // x rounded to tf32
__device__ float  g_wqkvr[NQKV*DIM];          // w_qkv rounded to tf32
__device__ float  g_wprojr[DIM*DIM];          // w_proj rounded to tf32

// ---------------------------------------------------------------------------
// helpers
// ---------------------------------------------------------------------------
__device__ __forceinline__ uint32_t f2tf32(float f) {
    uint32_t u;
    asm("cvt.rna.tf32.f32 %0, %1;" : "=r"(u) : "f"(f));
    return u;
}
__device__ __forceinline__ float ftf32(float f) { return __uint_as_float(f2tf32(f)); }

__device__ __forceinline__ float ex2(float x) {
    float r;
    asm("ex2.approx.f32 %0, %1;" : "=f"(r) : "f"(x));
    return r;
}

__device__ __forceinline__ uint32_t pack_f16x2(float hi, float lo) {
    uint32_t r;
    asm("cvt.rn.f16x2.f32 %0, %1, %2;" : "=r"(r) : "f"(hi), "f"(lo));
    return r;   // lo -> lower 16 bits, hi -> upper 16 bits
}

__device__ __forceinline__ void mma_tf32(float c[4], const uint32_t a[4], const uint32_t b[2]) {
    asm volatile(
        "mma.sync.aligned.m16n8k8.row.col.f32.tf32.tf32.f32 "
        "{%0,%1,%2,%3},{%4,%5,%6,%7},{%8,%9},{%0,%1,%2,%3};\n"
        : "+f"(c[0]), "+f"(c[1]), "+f"(c[2]), "+f"(c[3])
        : "r"(a[0]), "r"(a[1]), "r"(a[2]), "r"(a[3]), "r"(b[0]), "r"(b[1]));
}

__device__ __forceinline__ void mma_f16(float c[4], const uint32_t a[4], const uint32_t b[2]) {
    asm volatile(
        "mma.sync.aligned.m16n8k16.row.col.f32.f16.f16.f32 "
        "{%0,%1,%2,%3},{%4,%5,%6,%7},{%8,%9},{%0,%1,%2,%3};\n"
        : "+f"(c[0]), "+f"(c[1]), "+f"(c[2]), "+f"(c[3])
        : "r"(a[0]), "r"(a[1]), "r"(a[2]), "r"(a[3]), "r"(b[0]), "r"(b[1]));
}

// ---------------------------------------------------------------------------
// Fused tf32 rounding pre-pass (RNA) for x, w_qkv, w_proj in ONE launch.
// ---------------------------------------------------------------------------
#define N4X (MROWS*DIM/4)
#define N4Q (NQKV*DIM/4)
#define N4P (DIM*DIM/4)
#define N4TOT (N4X + N4Q + N4P)

__global__ __launch_bounds__(256)
void round3_kernel(const float* __restrict__ x,  float* __restrict__ xo,
                   const float* __restrict__ wq, float* __restrict__ wqo,
                   const float* __restrict__ wp, float* __restrict__ wpo)
{
    int i = blockIdx.x * 256 + threadIdx.x;
    const float4* in; float4* out; int j;
    if (i < N4X)            { in = (const float4*)x;  out = (float4*)xo;  j = i; }
    else if (i < N4X + N4Q) { in = (const float4*)wq; out = (float4*)wqo; j = i - N4X; }
    else if (i < N4TOT)     { in = (const float4*)wp; out = (float4*)wpo; j = i - N4X - N4Q; }
    else return;
    float4 v = in[j];
    out[j] = make_float4(ftf32(v.x), ftf32(v.y), ftf32(v.z), ftf32(v.w));
}

// ---------------------------------------------------------------------------
// V transpose kernel: g_vh [bh][s][d] (fp16) -> g_vt [bh][d][s] (fp16)
// ---------------------------------------------------------------------------
__global__ __launch_bounds__(256)
void vtrans_kernel()
{
    __shared__ __half tile[64][65];
    const int bh = blockIdx.y;
    const int s0 = blockIdx.x * 64;
    const __half* src = g_vh + ((long)bh*SEQ + s0)*HD;
    __half* dst = g_vt + (long)bh*HD*SEQ + s0;
    const int t = threadIdx.x;
#pragma unroll
    for (int i = 0; i < 16; ++i) {
        const int idx = t + i*256;
        const int r = idx >> 6, c = idx & 63;
        tile[r][c] = src[r*HD + c];
    }
    __syncthreads();
#pragma unroll
    for (int i = 0; i < 16; ++i) {
        const int idx = t + i*256;
        const int d = idx >> 6, s = idx & 63;
        dst[(long)d*SEQ + s] = tile[s][d];
    }
}

// ---------------------------------------------------------------------------
// TF32 GEMM (R13 config — measured best): C[m,n] = sum_k A[m,k]*W[n,k]+bias[n]
// BM=BN=128, BK=32, 256 threads, cp.async 2-stage, warp tile 32x64.
// SCATTER=1: q/k fp32(tf32-rounded), v fp16 into g_vh.
// ---------------------------------------------------------------------------
#define PK 36
#define GEMM_SMEM (2*2*128*PK*4)   // 73728 bytes

template<int SCATTER>
__global__ __launch_bounds__(256)
void gemm_tf32(const float* __restrict__ A,
               const float* __restrict__ W,
               const float* __restrict__ bias,
               float* __restrict__ out)
{
    extern __shared__ float sm[];
    float* As = sm;               // [2][128][PK]
    float* Bs = sm + 2*128*PK;    // [2][128][PK]

    const int tid  = threadIdx.x;
    const int wid  = tid >> 5;
    const int lane = tid & 31;
    const int m0 = blockIdx.y * 128;
    const int n0 = blockIdx.x * 128;
    const int wm = (wid & 3) * 32;
    const int wn = (wid >> 2) * 64;
    const int tg = lane >> 2;
    const int tk = lane & 3;

    float acc[2][8][4];
#pragma unroll
    for (int mt = 0; mt < 2; ++mt)
#pragma unroll
        for (int nt = 0; nt < 8; ++nt)
#pragma unroll
            for (int c = 0; c < 4; ++c) acc[mt][nt][c] = 0.f;

    const int K = 1024;
    const int NS = K / 32;

    auto stage = [&](int s, int buf) {
        const int k0 = s * 32;
#pragma unroll
        for (int i = 0; i < 4; ++i) {
            const int t   = tid + i * 256;
            const int row = t >> 3;
            const int kc  = (t & 7) << 2;
            uint32_t sa = (uint32_t)__cvta_generic_to_shared(
                &As[buf*128*PK + row*PK + kc]);
            asm volatile("cp.async.cg.shared.global [%0], [%1], 16;\n"
                         :: "r"(sa), "l"(&A[(long)(m0 + row) * K + k0 + kc]));
            uint32_t sb = (uint32_t)__cvta_generic_to_shared(
                &Bs[buf*128*PK + row*PK + kc]);
            asm volatile("cp.async.cg.shared.global [%0], [%1], 16;\n"
                         :: "r"(sb), "l"(&W[(long)(n0 + row) * K + k0 + kc]));
        }
        asm volatile("cp.async.commit_group;\n");
    };

    stage(0, 0);

    for (int s = 0; s < NS; ++s) {
        const int buf = s & 1;
        if (s + 1 < NS) {
            stage(s + 1, buf ^ 1);
            asm volatile("cp.async.wait_group 1;\n");
        } else {
            asm volatile("cp.async.wait_group 0;\n");
        }
        __syncthreads();

        const float* as = &As[buf*128*PK];
        const float* bs = &Bs[buf*128*PK];
#pragma unroll
        for (int k8 = 0; k8 < 32; k8 += 8) {
            uint32_t af[2][4], bf[8][2];
#pragma unroll
            for (int mt = 0; mt < 2; ++mt) {
                const float* p = &as[(wm + mt*16 + tg)*PK + k8 + tk];
                af[mt][0] = __float_as_uint(p[0]);
                af[mt][1] = __float_as_uint(p[8*PK]);
                af[mt][2] = __float_as_uint(p[4]);
                af[mt][3] = __float_as_uint(p[8*PK + 4]);
            }
#pragma unroll
            for (int nt = 0; nt < 8; ++nt) {
                const float* p = &bs[(wn + nt*8 + tg)*PK + k8 + tk];
                bf[nt][0] = __float_as_uint(p[0]);
                bf[nt][1] = __float_as_uint(p[4]);
            }
#pragma unroll
            for (int mt = 0; mt < 2; ++mt)
#pragma unroll
                for (int nt = 0; nt < 8; ++nt)
                    mma_tf32(acc[mt][nt], af[mt], bf[nt]);
        }
        __syncthreads();
    }

    // epilogue (float2 / half2 stores)
#pragma unroll
    for (int mt = 0; mt < 2; ++mt) {
#pragma unroll
        for (int nt = 0; nt < 8; ++nt) {
            const int n = n0 + wn + nt*8 + 2*tk;
#pragma unroll
            for (int half = 0; half < 2; ++half) {
                const int m = m0 + wm + mt*16 + tg + half*8;
                const float v0 = acc[mt][nt][half*2]     + bias[n];
                const float v1 = acc[mt][nt][half*2 + 1] + bias[n + 1];
                if (SCATTER) {
                    const int b = m >> 11, sq = m & 2047;
                    const int part = n >> 10, h = (n >> 6) & 15, d = n & 63;
                    const long idx = ((((long)b*HEADS + h)*SEQ) + sq)*HD + d;
                    if (part == 0) {
                        *(float2*)&g_q[idx] = make_float2(ftf32(v0), ftf32(v1));
                    } else if (part == 1) {
                        *(float2*)&g_k[idx] = make_float2(ftf32(v0), ftf32(v1));
                    } else {
                        *(__half2*)&g_vh[idx] = __floats2half2_rn(v0, v1);
                    }
                } else {
                    *(float2*)&out[(long)m * 1024 + n] = make_float2(v0, v1);
                }
            }
        }
    }
}

// ---------------------------------------------------------------------------
// Flash attention v5: tf32 QK^T + fp16 PV (m16n8k16), base-2 softmax.
// BQ=128, BKV=64, 256 threads = 8 warps; each warp owns 16 rows.
// K smem fp32 pitch 68; V smem fp16 [d][kv] pitch 72 halves (36 words);
// P smem fp16 per warp [16][72 halves].
// ---------------------------------------------------------------------------
#define KP5 68
#define VW5 36                      // V pitch in 32-bit words
#define PW5 36                      // P pitch in 32-bit words
#define F5_KOFF 0
#define F5_VOFF (2*64*KP5)          // 8704 floats
#define F5_POFF (F5_VOFF + 2*64*VW5)  // + 4608 -> 13312 floats
#define F5_SMEM ((F5_POFF + 8*16*PW5)*4)   // 71680 bytes

__global__ __launch_bounds__(256, 2)
void flash5(float* __restrict__ Ob)
{
    extern __shared__ float sm[];
    float*    Ksm = sm + F5_KOFF;                    // [2][64][KP5] fp32
    uint32_t* Vsm = (uint32_t*)(sm + F5_VOFF);       // [2][64][VW5] fp16x2
    uint32_t* Psm = (uint32_t*)(sm + F5_POFF);       // [8][16][PW5] fp16x2

    const int tid  = threadIdx.x;
    const int wid  = tid >> 5;
    const int lane = tid & 31;
    const int tg = lane >> 2;
    const int tk = lane & 3;
    const int bh = blockIdx.y;
    const int q0 = blockIdx.x * 128;
    const int wm = wid * 16;

    const float*  Qg = g_q + ((long)bh*SEQ + q0) * HD;
    const float*  Kg = g_k + (long)bh*SEQ*HD;
    const __half* Vg = g_vt + (long)bh*HD*SEQ;       // [d][s]
    uint32_t* Pw = Psm + wid*16*PW5;

    const float qs = 0.125f * 1.4426950408889634f;
    uint32_t qf[8][4];
#pragma unroll
    for (int i = 0; i < 8; ++i) {
        const int k = i * 8;
        qf[i][0] = f2tf32(Qg[(wm+tg)*HD   + k+tk]   * qs);
        qf[i][1] = f2tf32(Qg[(wm+tg+8)*HD + k+tk]   * qs);
        qf[i][2] = f2tf32(Qg[(wm+tg)*HD   + k+tk+4] * qs);
        qf[i][3] = f2tf32(Qg[(wm+tg+8)*HD + k+tk+4] * qs);
    }

    float oacc[8][4];
#pragma unroll
    for (int nt = 0; nt < 8; ++nt)
#pragma unroll
        for (int c = 0; c < 4; ++c) oacc[nt][c] = 0.f;
    float m0 = -1e30f, m1 = -1e30f, l0 = 0.f, l1 = 0.f;

    auto stage = [&](int s, int b2) {
        const float* Kt = Kg + (long)s*64*HD;
#pragma unroll
        for (int i = 0; i < 4; ++i) {        // K: 64x64 fp32 = 1024 f4
            const int t = tid + i*256;
            const int r = t >> 4;
            const int c = (t & 15) << 2;
            uint32_t dk = (uint32_t)__cvta_generic_to_shared(
                &Ksm[b2*64*KP5 + r*KP5 + c]);
            asm volatile("cp.async.cg.shared.global [%0], [%1], 16;\n"
                         :: "r"(dk), "l"(&Kt[r*HD + c]));
        }
#pragma unroll
        for (int i = 0; i < 2; ++i) {        // V: 64 d-rows x 128B = 512 chunks
            const int t = tid + i*256;
            const int d = t >> 3;            // 0..63
            const int c = t & 7;             // 16B chunk
            uint32_t dv = (uint32_t)__cvta_generic_to_shared(
                &Vsm[b2*64*VW5 + d*VW5 + c*4]);
            asm volatile("cp.async.cg.shared.global [%0], [%1], 16;\n"
                         :: "r"(dv), "l"(Vg + (long)d*SEQ + s*64 + c*8));
        }
        asm volatile("cp.async.commit_group;\n");
    };

    stage(0, 0);

    const int NT = SEQ / 64;
    for (int kt = 0; kt < NT; ++kt) {
        const int buf = kt & 1;
        asm volatile("cp.async.wait_group 0;\n");
        __syncthreads();
        if (kt + 1 < NT) stage(kt + 1, buf ^ 1);

        const float*    Kb = &Ksm[buf*64*KP5];
        const uint32_t* Vb = &Vsm[buf*64*VW5];

        // ---- S2 = (Q*qs) K^T : tf32, 16x64 per warp ----
        float sacc[8][4];
#pragma unroll
        for (int nt = 0; nt < 8; ++nt)
#pragma unroll
            for (int c = 0; c < 4; ++c) sacc[nt][c] = 0.f;
#pragma unroll
        for (int i = 0; i < 8; ++i) {
            const int k8 = i * 8;
            uint32_t bf[8][2];
#pragma unroll
            for (int nt = 0; nt < 8; ++nt) {
                const float* p = &Kb[(nt*8 + tg)*KP5 + k8 + tk];
                bf[nt][0] = __float_as_uint(p[0]);
                bf[nt][1] = __float_as_uint(p[4]);
            }
#pragma unroll
            for (int nt = 0; nt < 8; ++nt)
                mma_tf32(sacc[nt], qf[i], bf[nt]);
        }

        // ---- online softmax (base 2), in registers; P packed to fp16 ----
        float r0 = -1e30f, r1 = -1e30f;
#pragma unroll
        for (int nt = 0; nt < 8; ++nt) {
            r0 = fmaxf(r0, fmaxf(sacc[nt][0], sacc[nt][1]));
            r1 = fmaxf(r1, fmaxf(sacc[nt][2], sacc[nt][3]));
        }
        r0 = fmaxf(r0, __shfl_xor_sync(0xffffffffu, r0, 1));
        r0 = fmaxf(r0, __shfl_xor_sync(0xffffffffu, r0, 2));
        r1 = fmaxf(r1, __shfl_xor_sync(0xffffffffu, r1, 1));
        r1 = fmaxf(r1, __shfl_xor_sync(0xffffffffu, r1, 2));
        const float mn0 = fmaxf(m0, r0);
        const float mn1 = fmaxf(m1, r1);
        const float a0 = ex2(m0 - mn0);
        const float a1 = ex2(m1 - mn1);
        float s0 = 0.f, s1 = 0.f;
#pragma unroll
        for (int nt = 0; nt < 8; ++nt) {
            const float p0 = ex2(sacc[nt][0] - mn0);
            const float p1 = ex2(sacc[nt][1] - mn0);
            const float p2 = ex2(sacc[nt][2] - mn1);
            const float p3 = ex2(sacc[nt][3] - mn1);
            s0 += p0 + p1;
            s1 += p2 + p3;
            Pw[tg*PW5     + nt*4 + tk] = pack_f16x2(p1, p0);
            Pw[(tg+8)*PW5 + nt*4 + tk] = pack_f16x2(p3, p2);
        }
        s0 += __shfl_xor_sync(0xffffffffu, s0, 1);
        s0 += __shfl_xor_sync(0xffffffffu, s0, 2);
        s1 += __shfl_xor_sync(0xffffffffu, s1, 1);
        s1 += __shfl_xor_sync(0xffffffffu, s1, 2);
        l0 = l0 * a0 + s0;
        l1 = l1 * a1 + s1;
        m0 = mn0; m1 = mn1;
#pragma unroll
        for (int nt = 0; nt < 8; ++nt) {
            oacc[nt][0] *= a0; oacc[nt][1] *= a0;
            oacc[nt][2] *= a1; oacc[nt][3] *= a1;
        }
        __syncwarp();

        // ---- O += P @ V : fp16 m16n8k16, 4 K-steps ----
#pragma unroll
        for (int ks = 0; ks < 4; ++ks) {
            const int k32 = ks * 8;   // 32-bit word offset (16 halves per step)
            uint32_t af[4];
            af[0] = Pw[tg*PW5     + k32 + tk];
            af[1] = Pw[(tg+8)*PW5 + k32 + tk];
            af[2] = Pw[tg*PW5     + k32 + tk + 4];
            af[3] = Pw[(tg+8)*PW5 + k32 + tk + 4];
            uint32_t bf[8][2];
#pragma unroll
            for (int nt = 0; nt < 8; ++nt) {
                const uint32_t* p = &Vb[(nt*8 + tg)*VW5 + k32 + tk];
                bf[nt][0] = p[0];
                bf[nt][1] = p[4];
            }
#pragma unroll
            for (int nt = 0; nt < 8; ++nt)
                mma_f16(oacc[nt], af, bf[nt]);
        }
    }

    // ---- finalize + store (tf32-rounded) to [B,S,D] ----
    const int b = bh >> 4, h = bh & 15;
    const float i0 = 1.f / l0;
    const float i1 = 1.f / l1;
    const long row0 = (long)b*SEQ + q0 + wm + tg;
    const long row1 = row0 + 8;
#pragma unroll
    for (int nt = 0; nt < 8; ++nt) {
        const int col = h*HD + nt*8 + 2*tk;
        *(float2*)&Ob[row0*DIM + col] =
            make_float2(ftf32(oacc[nt][0]*i0), ftf32(oacc[nt][1]*i0));
        *(float2*)&Ob[row1*DIM + col] =
            make_float2(ftf32(oacc[nt][2]*i1), ftf32(oacc[nt][3]*i1));
    }
}

// ---------------------------------------------------------------------------
extern "C" void kernel_launch(void* const* d_in, const int* in_sizes, int n_in,
                              void* d_out, int out_size)
{
    const float* x      = (const float*)d_in[0];
    const float* w_qkv  = (const float*)d_in[1];
    const float* b_qkv  = (const float*)d_in[2];
    const float* w_proj = (const float*)d_in[3];
    const float* b_proj = (const float*)d_in[4];
    float* out = (float*)d_out;

    float *attn_ptr = nullptr, *xr = nullptr, *wqkvr = nullptr, *wprojr = nullptr;
    cudaGetSymbolAddress((void**)&attn_ptr, g_attn);
    cudaGetSymbolAddress((void**)&xr, g_xr);
    cudaGetSymbolAddress((void**)&wqkvr, g_wqkvr);
    cudaGetSymbolAddress((void**)&wprojr, g_wprojr);

    cudaFuncSetAttribute(gemm_tf32<1>,
        cudaFuncAttributeMaxDynamicSharedMemorySize, GEMM_SMEM);
    cudaFuncSetAttribute(gemm_tf32<0>,
        cudaFuncAttributeMaxDynamicSharedMemorySize, GEMM_SMEM);
    cudaFuncSetAttribute(flash5,
        cudaFuncAttributeMaxDynamicSharedMemorySize, F5_SMEM);

    // 0) fused tf32 rounding pre-pass (RNA) for all GEMM operands
    round3_kernel<<<(N4TOT + 255)/256, 256>>>(x, xr, w_qkv, wqkvr, w_proj, wprojr);

    // 1) QKV GEMM + bias -> Q/K fp32 (tf32-rounded), V fp16 [b,h,s,d]
    {
        dim3 grid(NQKV/128, MROWS/128);   // (24, 32)
        gemm_tf32<1><<<grid, 256, GEMM_SMEM>>>(xr, wqkvr, b_qkv, nullptr);
    }
    // 1b) V transpose fp16: [b,h,s,d] -> [b,h,d,s]
    {
        dim3 grid(SEQ/64, BATCH*HEADS);   // (32, 32)
        vtrans_kernel<<<grid, 256>>>();
    }
    // 2) flash attention v5 -> g_attn [b,s,D] (tf32-rounded)
    {
        dim3 grid(SEQ/128, BATCH*HEADS);  // (16, 32)
        flash5<<<grid, 256, F5_SMEM>>>(attn_ptr);
    }
    // 3) output projection + bias -> d_out
    {
        dim3 grid(DIM/128, MROWS/128);    // (8, 32)
        gemm_tf32<0><<<grid, 256, GEMM_SMEM>>>(attn_ptr, wprojr, b_proj, out);
    }
}